// round 15
// baseline (speedup 1.0000x reference)
#include <cuda_runtime.h>
#include <math.h>

// Problem constants
#define Bc   128
#define Tc   600
#define Uc   96
#define Kc   10
#define CDc  80
#define Sc   512
#define OUTD 121
#define KT1  595     // cell1 fused K: 3 + 80 + 512
#define KT2  1107    // cell2/3 fused K: 3 + 512 + 80 + 512
#define KP1  640     // padded to 5 stages of 128
#define KP2  1152    // padded to 9 stages of 128
#define NBLK 128
#define NTHR 512

// ---------------- persistent device state (static, no allocations) --------------
__device__ __align__(16) float g_Wf1[KP1 * 1024];  // interleaved j/k cols, zero-padded
__device__ __align__(16) float g_Wf2[KP2 * 1024];
__device__ __align__(16) float g_bf1[1024];
__device__ __align__(16) float g_bf2[1024];
__device__ __align__(16) float g_h1[2][Bc * Sc];
__device__ __align__(16) float g_h2[2][Bc * Sc];
__device__ __align__(16) float g_h3[2][Bc * Sc];
__device__ float g_kappa[Bc * Kc];
__device__ float g_w[Bc * CDc];
__device__ float g_kgpart[16][Bc][30];
__device__ __align__(16) float g_ys[(size_t)Bc * Tc * Sc];
// per-group barrier state, 128B-strided
__device__ unsigned g_gcnt[8 * 32];
__device__ volatile unsigned g_ggen[8 * 32];

// Dynamic smem layout (floats), stage = 128 k-rows, 16 k-groups x 8 k-rows:
//   two stage buffers, buffer b at b*BUF_F:
//     Ws: 16 groups x 8 k x 64 cols   at +0      (8192 floats)
//     As: 16 groups x 8 k x 16 pitch  at +8192   (2048 floats)
//   post-loop reuse (spans both buffers):
//     red:   16 groups x 16 b x 64 cols at +0    (16384 floats)
//     htile: 16 b x 34                  at +16384
#define BUF_F   10752
#define AS_OFF  8192
#define A_PITCH 16
#define HT_OFF  16384
#define SMEM_BYTES (2 * BUF_F * 4)

// ---------------- per-group barrier (16 blocks, monotonic, pure spin) -----------
__device__ __forceinline__ void group_bar(int group, unsigned nbar)
{
    __threadfence();
    __syncthreads();
    if (threadIdx.x == 0) {
        const int slot = group * 32;
        unsigned v = atomicAdd(&g_gcnt[slot], 1) + 1;
        if (v == nbar * 16u) {
            __threadfence();
            g_ggen[slot] = nbar;
        }
        while (g_ggen[slot] < nbar) { }
    }
    __syncthreads();
}

// ---------------- prep kernels (split 5-way so ncu's skip-5 lands on rnn) -------
__global__ void prep_w1(const float* __restrict__ Wjx1, const float* __restrict__ Wkx1,
                        const float* __restrict__ Wjh1, const float* __restrict__ Wkh1)
{
    const int stride = gridDim.x * blockDim.x;
    for (int idx = blockIdx.x * blockDim.x + threadIdx.x; idx < KP1 * 1024; idx += stride) {
        int d = idx >> 10, c = idx & 1023;
        int s = c >> 1, isk = c & 1;
        float v = 0.f;
        if (d < 83)        v = isk ? Wkx1[d * Sc + s] : Wjx1[d * Sc + s];
        else if (d < KT1)  v = isk ? Wkh1[(d - 83) * Sc + s] : Wjh1[(d - 83) * Sc + s];
        g_Wf1[idx] = v;
    }
}

__global__ void prep_w2a(const float* __restrict__ Wjx2, const float* __restrict__ Wkx2)
{
    const int stride = gridDim.x * blockDim.x;
    for (int idx = blockIdx.x * blockDim.x + threadIdx.x; idx < 576 * 1024; idx += stride) {
        int d = idx >> 10, c = idx & 1023;
        int s = c >> 1, isk = c & 1;
        g_Wf2[idx] = isk ? Wkx2[d * Sc + s] : Wjx2[d * Sc + s];
    }
}

__global__ void prep_w2b(const float* __restrict__ Wjx2, const float* __restrict__ Wkx2,
                         const float* __restrict__ Wjh2, const float* __restrict__ Wkh2)
{
    const int stride = gridDim.x * blockDim.x;
    for (int i = blockIdx.x * blockDim.x + threadIdx.x; i < (KP2 - 576) * 1024; i += stride) {
        int idx = i + 576 * 1024;
        int d = idx >> 10, c = idx & 1023;
        int s = c >> 1, isk = c & 1;
        float v = 0.f;
        if (d < 595)       v = isk ? Wkx2[d * Sc + s] : Wjx2[d * Sc + s];
        else if (d < KT2)  v = isk ? Wkh2[(d - 595) * Sc + s] : Wjh2[(d - 595) * Sc + s];
        g_Wf2[idx] = v;
    }
}

__global__ void prep_bias(const float* __restrict__ bjx1, const float* __restrict__ bjh1,
                          const float* __restrict__ bkx1, const float* __restrict__ bkh1,
                          const float* __restrict__ bjx2, const float* __restrict__ bjh2,
                          const float* __restrict__ bkx2, const float* __restrict__ bkh2)
{
    const int stride = gridDim.x * blockDim.x;
    const int t0 = blockIdx.x * blockDim.x + threadIdx.x;
    for (int i = t0; i < 8 * 32; i += stride) { g_gcnt[i] = 0; g_ggen[i] = 0; }
    for (int idx = t0; idx < 1024; idx += stride) {
        int s = idx >> 1, isk = idx & 1;
        g_bf1[idx] = isk ? (bkx1[s] + bkh1[s]) : (bjx1[s] + bjh1[s]);
        g_bf2[idx] = isk ? (bkx2[s] + bkh2[s]) : (bjx2[s] + bjh2[s]);
    }
}

__global__ void prep_state()
{
    const int stride = gridDim.x * blockDim.x;
    const int t0 = blockIdx.x * blockDim.x + threadIdx.x;
    for (int idx = t0; idx < Bc * Sc; idx += stride) {
        g_h1[0][idx] = 0.f; g_h1[1][idx] = 0.f;
        g_h2[0][idx] = 0.f; g_h2[1][idx] = 0.f;
        g_h3[0][idx] = 0.f; g_h3[1][idx] = 0.f;
    }
    for (int idx = t0; idx < Bc * CDc; idx += stride) g_w[idx] = 0.f;
    for (int idx = t0; idx < Bc * Kc; idx += stride) g_kappa[idx] = 0.f;
}

// ---------------- gated-cell GEMM phase -----------------------------------------
// Group-local: 16 blocks x 16 batches. Tile 16b x 64c; 16 warps = 16 k-groups of
// 8 k-rows per 128-k stage; thread tile 4b x 8c; scalar FFMA; cp.async W tiles.
template <int CELL>
__device__ void cell_phase(float* sm, const float* __restrict__ x,
                           const float* __restrict__ W_win, int t)
{
    constexpr int KT = (CELL == 1) ? KT1 : KT2;
    constexpr int NS = (CELL == 1) ? 5 : 9;

    const int pi = t & 1;
    const float* __restrict__ Wf    = (CELL == 1) ? g_Wf1 : g_Wf2;
    const float* __restrict__ bf    = (CELL == 1) ? g_bf1 : g_bf2;
    const float* __restrict__ h_old = (CELL == 1) ? g_h1[pi ^ 1]
                                   : (CELL == 2) ? g_h2[pi ^ 1] : g_h3[pi ^ 1];
    float* __restrict__       h_new = (CELL == 1) ? g_h1[pi]
                                   : (CELL == 2) ? g_h2[pi] : g_h3[pi];
    const float* __restrict__ hin   = (CELL == 2) ? g_h1[pi] : g_h2[pi];

    const int tid  = threadIdx.x;
    const int kg   = tid >> 5;      // warp = k-group 0..15
    const int lane = tid & 31;
    const int bb   = lane >> 3;     // 0..3 -> 4 b's each (FMA loop)
    const int cc   = lane & 7;      // 0..7 -> 8 cols each
    const int kl   = lane & 7;      // k-row within group (gather/store)
    const int bq   = lane >> 3;     // batch quarter (gather/store)
    const int bid  = blockIdx.x;
    const int c0 = (bid & 15) * 64;
    const int b0 = (bid >> 4) * 16;

    const unsigned smbase = (unsigned)__cvta_generic_to_shared(sm);

    float acc[4][8];
#pragma unroll
    for (int i = 0; i < 4; i++)
#pragma unroll
        for (int j = 0; j < 8; j++) acc[i][j] = 0.f;

    float areg[4];

    auto issueW = [&](int s, int buf) {
        const int k0 = s * 128 + kg * 8;
        const float* wsrc = Wf + (size_t)k0 * 1024 + c0;
        unsigned dst = smbase + (unsigned)((buf * BUF_F + kg * 512) * 4);
#pragma unroll
        for (int i = 0; i < 4; i++) {
            int idx = lane + i * 32;          // 0..127 float4 slots (8 rows x 16)
            int row = idx >> 4, co = (idx & 15) * 4;
            unsigned d = dst + (unsigned)((row * 64 + co) * 4);
            const float* sp = wsrc + row * 1024 + co;
            asm volatile("cp.async.cg.shared.global [%0], [%1], 16;"
                         :: "r"(d), "l"(sp) : "memory");
        }
        asm volatile("cp.async.commit_group;" ::: "memory");
    };
    auto gatherA = [&](int s) {
        const int k = s * 128 + kg * 8 + kl;   // this lane's k-row
#pragma unroll
        for (int i = 0; i < 4; i++) {
            int b = b0 + bq * 4 + i;
            float v = 0.f;
            if (k < KT) {
                if (CELL == 1) {
                    if (k < 3)       v = x[b * (Tc * 3) + t * 3 + k];
                    else if (k < 83) v = __ldcg(&g_w[b * CDc + (k - 3)]);
                    else             v = __ldcg(&h_old[b * Sc + (k - 83)]);
                } else {
                    if (k < 3)        v = x[b * (Tc * 3) + t * 3 + k];
                    else if (k < 515) v = __ldcg(&hin[b * Sc + (k - 3)]);
                    else if (k < 595) v = __ldcg(&g_w[b * CDc + (k - 515)]);
                    else              v = __ldcg(&h_old[b * Sc + (k - 595)]);
                }
            }
            areg[i] = v;
        }
    };
    auto storeA = [&](int buf) {
        float* arow = sm + buf * BUF_F + AS_OFF + kg * (8 * A_PITCH) + kl * A_PITCH
                      + bq * 4;
        *(float4*)(arow) = make_float4(areg[0], areg[1], areg[2], areg[3]);
    };

    // prologue: stage 0 into buffer 0
    issueW(0, 0);
    gatherA(0);
    storeA(0);
    asm volatile("cp.async.wait_group 0;" ::: "memory");
    __syncthreads();

    int buf = 0;
    for (int s = 0; s < NS; ++s) {
        if (s + 1 < NS) { issueW(s + 1, buf ^ 1); gatherA(s + 1); }

        const float* wrow = sm + buf * BUF_F + kg * 512;
        const float* arow = sm + buf * BUF_F + AS_OFF + kg * (8 * A_PITCH);
#pragma unroll
        for (int k = 0; k < 8; ++k) {
            float4 a  = *(const float4*)(arow + k * A_PITCH + bb * 4);
            float4 w0 = *(const float4*)(wrow + k * 64 + cc * 8);
            float4 w1 = *(const float4*)(wrow + k * 64 + cc * 8 + 4);
            float av[4] = {a.x, a.y, a.z, a.w};
            float wv[8] = {w0.x, w0.y, w0.z, w0.w, w1.x, w1.y, w1.z, w1.w};
#pragma unroll
            for (int ib = 0; ib < 4; ib++)
#pragma unroll
                for (int jc = 0; jc < 8; jc++)
                    acc[ib][jc] += av[ib] * wv[jc];
        }

        if (s + 1 < NS) storeA(buf ^ 1);
        asm volatile("cp.async.wait_group 0;" ::: "memory");
        __syncthreads();
        buf ^= 1;
    }

    // ---- dump k-split partials to red[16][16][64] (spans both buffers) ----
    float* red = sm;
#pragma unroll
    for (int ib = 0; ib < 4; ib++) {
        int b = bb * 4 + ib;
        float* dst = red + (kg * 16 + b) * 64 + cc * 8;
        *(float4*)(dst)     = make_float4(acc[ib][0], acc[ib][1], acc[ib][2], acc[ib][3]);
        *(float4*)(dst + 4) = make_float4(acc[ib][4], acc[ib][5], acc[ib][6], acc[ib][7]);
    }
    __syncthreads();

    // ---- reduce 16 partials + bias, gate-combine: 1 s-unit per thread ----
    {
        const int b_loc = tid >> 5;     // 0..15
        const int sp    = tid & 31;     // 0..31 -> cols sp*2, sp*2+1
        float2 e = *(const float2*)&bf[c0 + sp * 2];
#pragma unroll
        for (int g = 0; g < 16; g++) {
            float2 v = *(const float2*)(red + (g * 16 + b_loc) * 64 + sp * 2);
            e.x += v.x; e.y += v.y;
        }
        const int b  = b0 + b_loc;
        const int s0 = (c0 >> 1) + sp;
        float hold = h_old[b * Sc + s0];
        float jv = 1.f / (1.f + __expf(-e.x));
        float kv = 1.f / (1.f + __expf(-e.y));
        float hn = jv * (1.f - hold) + (1.f - kv) * hold;
        h_new[b * Sc + s0] = hn;
        if (CELL == 3) g_ys[((size_t)b * Tc + t) * Sc + s0] = hn;
        if (CELL == 1) sm[HT_OFF + b_loc * 34 + sp] = hn;
    }

    // ---- cell1 only: window-head partials over this block's 32-s slice ----
    if (CELL == 1) {
        __syncthreads();
        const float* ht = sm + HT_OFF;
        if (tid < 240) {
            int bb2 = tid / 15, cp = tid % 15;
            int c  = cp * 2;
            int ct = bid & 15;
            int sbase = ct * 32;
            float a0 = 0.f, a1 = 0.f;
#pragma unroll 4
            for (int s2 = 0; s2 < 32; ++s2) {
                float hv = ht[bb2 * 34 + s2];
                a0 += hv * W_win[(sbase + s2) * 30 + c];
                a1 += hv * W_win[(sbase + s2) * 30 + c + 1];
            }
            g_kgpart[ct][b0 + bb2][c]     = a0;
            g_kgpart[ct][b0 + bb2][c + 1] = a1;
        }
    }
    __syncthreads();
}

// ---------------- attention window phase: each block owns ONE batch -------------
__device__ void attn_phase(float* sm, const float* __restrict__ c_vec,
                           const float* __restrict__ b_win)
{
    const int b = (blockIdx.x >> 4) * 16 + (blockIdx.x & 15);
    const int tid = threadIdx.x;
    float* abk = sm;          // [32]
    float* phi = sm + 32;     // [96]

    if (tid < 30) {
        float v = b_win[tid];
#pragma unroll
        for (int ct = 0; ct < 16; ++ct) v += __ldcg(&g_kgpart[ct][b][tid]);
        float e = __expf(v);
        if (tid >= 20) {
            int i = b * Kc + (tid - 20);
            float kn = g_kappa[i] + e;     // owner-only access
            g_kappa[i] = kn;
            abk[tid] = kn;
        } else {
            abk[tid] = e;
        }
    }
    __syncthreads();

    if (tid < Uc) {
        float u = (float)tid;
        float p = 0.f;
#pragma unroll
        for (int k = 0; k < Kc; ++k) {
            float d = abk[20 + k] - u;
            p += abk[k] * __expf(-abk[10 + k] * d * d);
        }
        phi[tid] = p;
    }
    __syncthreads();

    if (tid < CDc) {
        float acc = 0.f;
        const float* cv = c_vec + (size_t)b * Uc * CDc + tid;
#pragma unroll 4
        for (int u = 0; u < Uc; ++u) acc += phi[u] * __ldg(&cv[u * CDc]);
        g_w[b * CDc + tid] = acc;
    }
    __syncthreads();
}

// ---------------- persistent RNN kernel (8 independent 16-block groups) ---------
__global__ __launch_bounds__(NTHR, 1) void rnn_kernel(
    const float* __restrict__ x, const float* __restrict__ c_vec,
    const float* __restrict__ W_win, const float* __restrict__ b_win)
{
    extern __shared__ float sm[];
    const int group = blockIdx.x >> 4;
    unsigned nbar = 0;

    cell_phase<1>(sm, x, W_win, 0);
    group_bar(group, ++nbar);

    for (int t = 0; t < Tc; ++t) {
        attn_phase(sm, c_vec, b_win);
        group_bar(group, ++nbar);
        cell_phase<2>(sm, x, W_win, t);
        group_bar(group, ++nbar);
        cell_phase<3>(sm, x, W_win, t);
        if (t + 1 < Tc) cell_phase<1>(sm, x, W_win, t + 1);
        group_bar(group, ++nbar);
    }
}

// ---------------- final projection: out = ys @ W_lin + b_lin --------------------
__global__ __launch_bounds__(256) void final_kernel(
    const float* __restrict__ W_lin, const float* __restrict__ b_lin,
    float* __restrict__ out)
{
    __shared__ __align__(16) float As[16][68];
    __shared__ __align__(16) float Ws[16][128];

    const int tid = threadIdx.x;
    const int tcx = tid & 31;
    const int tr  = tid >> 5;
    const int r0 = blockIdx.x * 64;

    float acc[8][4];
#pragma unroll
    for (int i = 0; i < 8; i++)
#pragma unroll
        for (int j = 0; j < 4; j++) acc[i][j] = 0.f;

    for (int k0 = 0; k0 < Sc; k0 += 16) {
        {
            int r = tid >> 2, q = tid & 3;
            float4 v = *(const float4*)(g_ys + (size_t)(r0 + r) * Sc + k0 + q * 4);
            As[q * 4 + 0][r] = v.x; As[q * 4 + 1][r] = v.y;
            As[q * 4 + 2][r] = v.z; As[q * 4 + 3][r] = v.w;
        }
#pragma unroll
        for (int i = 0; i < 8; i++) {
            int idx = tid + i * 256;
            int r = idx >> 7, c = idx & 127;
            Ws[r][c] = (c < OUTD) ? W_lin[(k0 + r) * OUTD + c] : 0.f;
        }
        __syncthreads();
#pragma unroll
        for (int kk = 0; kk < 16; kk++) {
            float4 a0 = *(const float4*)(&As[kk][tr * 8]);
            float4 a1 = *(const float4*)(&As[kk][tr * 8 + 4]);
            float4 w  = *(const float4*)(&Ws[kk][tcx * 4]);
            float av[8] = {a0.x, a0.y, a0.z, a0.w, a1.x, a1.y, a1.z, a1.w};
#pragma unroll
            for (int i = 0; i < 8; i++) {
                acc[i][0] += av[i] * w.x; acc[i][1] += av[i] * w.y;
                acc[i][2] += av[i] * w.z; acc[i][3] += av[i] * w.w;
            }
        }
        __syncthreads();
    }

#pragma unroll
    for (int i = 0; i < 8; i++) {
        int row = r0 + tr * 8 + i;
#pragma unroll
        for (int j = 0; j < 4; j++) {
            int c = tcx * 4 + j;
            if (c < OUTD) out[(size_t)row * OUTD + c] = acc[i][j] + b_lin[c];
        }
    }
}

// ---------------- launch --------------------------------------------------------
extern "C" void kernel_launch(void* const* d_in, const int* in_sizes, int n_in,
                              void* d_out, int out_size)
{
    const float* x     = (const float*)d_in[0];
    const float* c_vec = (const float*)d_in[1];
    const float* W_win = (const float*)d_in[18];
    const float* b_win = (const float*)d_in[19];
    const float* W_lin = (const float*)d_in[20];
    const float* b_lin = (const float*)d_in[21];

    cudaFuncSetAttribute(rnn_kernel, cudaFuncAttributeMaxDynamicSharedMemorySize,
                         SMEM_BYTES);

    prep_w1<<<512, 256>>>((const float*)d_in[2], (const float*)d_in[6],
                          (const float*)d_in[4], (const float*)d_in[8]);
    prep_w2a<<<512, 256>>>((const float*)d_in[10], (const float*)d_in[14]);
    prep_w2b<<<512, 256>>>((const float*)d_in[10], (const float*)d_in[14],
                           (const float*)d_in[12], (const float*)d_in[16]);
    prep_bias<<<8, 256>>>((const float*)d_in[3],  (const float*)d_in[5],
                          (const float*)d_in[7],  (const float*)d_in[9],
                          (const float*)d_in[11], (const float*)d_in[13],
                          (const float*)d_in[15], (const float*)d_in[17]);
    prep_state<<<256, 256>>>();

    rnn_kernel<<<NBLK, NTHR, SMEM_BYTES>>>(x, c_vec, W_win, b_win);

    final_kernel<<<(Bc * Tc) / 64, 256>>>(W_lin, b_lin, (float*)d_out);
}

// round 16
// speedup vs baseline: 1.0730x; 1.0730x over previous
#include <cuda_runtime.h>
#include <math.h>

// Problem constants
#define Bc   128
#define Tc   600
#define Uc   96
#define Kc   10
#define CDc  80
#define Sc   512
#define OUTD 121
#define KT1  595     // cell1 fused K: 3 + 80 + 512
#define KT2  1107    // cell2/3 fused K: 3 + 512 + 80 + 512
#define KP1  640     // 5 stages of 128
#define KP2  1152    // 9 stages of 128
#define NBLK 128
#define NTHR 256

// ---------------- persistent device state (static, no allocations) --------------
__device__ __align__(16) float g_Wf1[KP1 * 1024];  // interleaved j/k cols, zero-padded
__device__ __align__(16) float g_Wf2[KP2 * 1024];
__device__ __align__(16) float g_bf1[1024];
__device__ __align__(16) float g_bf2[1024];
__device__ __align__(16) float g_h1[2][Bc * Sc];
__device__ __align__(16) float g_h2[2][Bc * Sc];
__device__ __align__(16) float g_h3[2][Bc * Sc];
__device__ float g_kappa[Bc * Kc];
__device__ float g_w[Bc * CDc];
__device__ float g_kgpart[16][Bc][30];
__device__ __align__(16) float g_ys[(size_t)Bc * Tc * Sc];
// per-group split-barrier counters: slot base = group*32; +0 = c3 (end of step),
// +8 = c1 (attn/w ready), +16 = c2 (h2 ready). Monotonic, never reset.
__device__ unsigned g_gcnt[8 * 32];

// Dynamic smem layout (floats), stage = 128 k-rows, 8 k-groups x 16 k-rows:
//   two stage buffers, buffer b at b*BUF_F:
//     Ws: 8 groups x 16 k x 64 cols   at +0      (8192 floats)
//     As: 8 groups x 16 k x 20 pitch  at +8192   (2560 floats)
//   post-loop reuse of buffer 0:
//     red:   8 groups x 16 b x 64 cols at +0     (8192 floats)
//     htile: 16 b x 34                 at +8192
//   attn scratch (never aliases buffers): at +2*BUF_F (128 floats)
#define BUF_F   10752
#define AS_OFF  8192
#define A_PITCH 20
#define SC_OFF  (2 * BUF_F)
#define SMEM_BYTES ((2 * BUF_F + 128) * 4)

// ---------------- split group barrier: arrive / wait ----------------------------
__device__ __forceinline__ void g_arrive(int slot)
{
    __threadfence();
    __syncthreads();
    if (threadIdx.x == 0) atomicAdd(&g_gcnt[slot], 1);
}
__device__ __forceinline__ void g_wait(int slot, unsigned target)
{
    if (threadIdx.x == 0) {
        while (*(volatile unsigned*)&g_gcnt[slot] < target) { }
    }
    __syncthreads();
}

// ---------------- prep kernels (3 launches; ncu capture lands on rnn) -----------
__global__ void prep_w1(const float* __restrict__ Wjx1, const float* __restrict__ Wkx1,
                        const float* __restrict__ Wjh1, const float* __restrict__ Wkh1)
{
    const int stride = gridDim.x * blockDim.x;
    for (int idx = blockIdx.x * blockDim.x + threadIdx.x; idx < KP1 * 1024; idx += stride) {
        int d = idx >> 10, c = idx & 1023;
        int s = c >> 1, isk = c & 1;
        float v = 0.f;
        if (d < 83)        v = isk ? Wkx1[d * Sc + s] : Wjx1[d * Sc + s];
        else if (d < KT1)  v = isk ? Wkh1[(d - 83) * Sc + s] : Wjh1[(d - 83) * Sc + s];
        g_Wf1[idx] = v;
    }
}

__global__ void prep_w2(const float* __restrict__ Wjx2, const float* __restrict__ Wkx2,
                        const float* __restrict__ Wjh2, const float* __restrict__ Wkh2)
{
    const int stride = gridDim.x * blockDim.x;
    for (int idx = blockIdx.x * blockDim.x + threadIdx.x; idx < KP2 * 1024; idx += stride) {
        int d = idx >> 10, c = idx & 1023;
        int s = c >> 1, isk = c & 1;
        float v = 0.f;
        if (d < 595)       v = isk ? Wkx2[d * Sc + s] : Wjx2[d * Sc + s];
        else if (d < KT2)  v = isk ? Wkh2[(d - 595) * Sc + s] : Wjh2[(d - 595) * Sc + s];
        g_Wf2[idx] = v;
    }
}

__global__ void prep_misc(const float* __restrict__ bjx1, const float* __restrict__ bjh1,
                          const float* __restrict__ bkx1, const float* __restrict__ bkh1,
                          const float* __restrict__ bjx2, const float* __restrict__ bjh2,
                          const float* __restrict__ bkx2, const float* __restrict__ bkh2)
{
    const int stride = gridDim.x * blockDim.x;
    const int t0 = blockIdx.x * blockDim.x + threadIdx.x;
    for (int i = t0; i < 8 * 32; i += stride) g_gcnt[i] = 0;
    for (int idx = t0; idx < 1024; idx += stride) {
        int s = idx >> 1, isk = idx & 1;
        g_bf1[idx] = isk ? (bkx1[s] + bkh1[s]) : (bjx1[s] + bjh1[s]);
        g_bf2[idx] = isk ? (bkx2[s] + bkh2[s]) : (bjx2[s] + bjh2[s]);
    }
    for (int idx = t0; idx < Bc * Sc; idx += stride) {
        g_h1[0][idx] = 0.f; g_h1[1][idx] = 0.f;
        g_h2[0][idx] = 0.f; g_h2[1][idx] = 0.f;
        g_h3[0][idx] = 0.f; g_h3[1][idx] = 0.f;
    }
    for (int idx = t0; idx < Bc * CDc; idx += stride) g_w[idx] = 0.f;
    for (int idx = t0; idx < Bc * Kc; idx += stride) g_kappa[idx] = 0.f;
}

// ---------------- attention (owner batch) — inlined into cell2 phase ------------
__device__ void attn_inline(float* sm, const float* __restrict__ c_vec,
                            const float* __restrict__ b_win)
{
    const int b = blockIdx.x;     // block (g,ct) owns batch g*16+ct == blockIdx.x
    const int tid = threadIdx.x;
    float* abk = sm + SC_OFF;     // [32]
    float* phi = sm + SC_OFF + 32; // [96]

    if (tid < 30) {
        float v = b_win[tid];
#pragma unroll
        for (int ct = 0; ct < 16; ++ct) v += __ldcg(&g_kgpart[ct][b][tid]);
        float e = __expf(v);
        if (tid >= 20) {
            int i = b * Kc + (tid - 20);
            float kn = g_kappa[i] + e;     // owner-only access
            g_kappa[i] = kn;
            abk[tid] = kn;
        } else {
            abk[tid] = e;
        }
    }
    __syncthreads();

    if (tid < Uc) {
        float u = (float)tid;
        float p = 0.f;
#pragma unroll
        for (int k = 0; k < Kc; ++k) {
            float d = abk[20 + k] - u;
            p += abk[k] * __expf(-abk[10 + k] * d * d);
        }
        phi[tid] = p;
    }
    __syncthreads();

    if (tid < CDc) {
        float acc = 0.f;
        const float* cv = c_vec + (size_t)b * Uc * CDc + tid;
#pragma unroll 4
        for (int u = 0; u < Uc; ++u) acc += phi[u] * __ldg(&cv[u * CDc]);
        g_w[b * CDc + tid] = acc;
    }
    // visibility handled by g_arrive (fence + sync) right after
}

// ---------------- gated-cell GEMM phase -----------------------------------------
// Tile 16b x 64c; 8 warps = 8 k-groups of 16 k-rows per 128-k stage; thread tile
// 4b x 8c; scalar FFMA; cp.async double-buffered W tiles.
// CELL 2/3 stage order: [5,6,7,8, 0,1,2,3,4] — old-state stages first, so the
// cross-block waits (and attn for CELL 2) hide behind dependency-free compute.
template <int CELL>
__device__ void cell_phase(float* sm, const float* __restrict__ x,
                           const float* __restrict__ W_win,
                           const float* __restrict__ c_vec,
                           const float* __restrict__ b_win,
                           int t, int group)
{
    constexpr int KT = (CELL == 1) ? KT1 : KT2;
    constexpr int NS = (CELL == 1) ? 5 : 9;

    const int pi = t & 1;
    const float* __restrict__ Wf    = (CELL == 1) ? g_Wf1 : g_Wf2;
    const float* __restrict__ bf    = (CELL == 1) ? g_bf1 : g_bf2;
    const float* __restrict__ h_old = (CELL == 1) ? g_h1[pi ^ 1]
                                   : (CELL == 2) ? g_h2[pi ^ 1] : g_h3[pi ^ 1];
    float* __restrict__       h_new = (CELL == 1) ? g_h1[pi]
                                   : (CELL == 2) ? g_h2[pi] : g_h3[pi];
    const float* __restrict__ hin   = (CELL == 2) ? g_h1[pi] : g_h2[pi];

    const int tid  = threadIdx.x;
    const int kg   = tid >> 5;      // warp = k-group 0..7
    const int lane = tid & 31;
    const int bb   = lane >> 3;     // 0..3 -> 4 b's each (FMA loop)
    const int cc   = lane & 7;      // 0..7 -> 8 cols each
    const int kl   = lane & 15;     // k-row within group (gather/store)
    const int bh   = lane >> 4;     // batch half (gather/store)
    const int bid  = blockIdx.x;
    const int c0 = (bid & 15) * 64;
    const int b0 = (bid >> 4) * 16;
    const int slot = group * 32;
    const unsigned tgt = (unsigned)(t + 1) * 16u;

    const unsigned smbase = (unsigned)__cvta_generic_to_shared(sm);

    float acc[4][8];
#pragma unroll
    for (int i = 0; i < 4; i++)
#pragma unroll
        for (int j = 0; j < 8; j++) acc[i][j] = 0.f;

    float areg[8];

    auto ord = [&](int si) -> int {
        return (CELL == 1) ? si : (si < 4 ? si + 5 : si - 4);
    };
    auto issueW = [&](int s, int buf) {
        const int k0 = s * 128 + kg * 16;
        const float* wsrc = Wf + (size_t)k0 * 1024 + c0;
        unsigned dst = smbase + (unsigned)((buf * BUF_F + kg * 1024) * 4);
#pragma unroll
        for (int i = 0; i < 8; i++) {
            int idx = lane + i * 32;          // 0..255 float4 slots (16 rows x 16)
            int row = idx >> 4, co = (idx & 15) * 4;
            unsigned d = dst + (unsigned)((row * 64 + co) * 4);
            const float* sp = wsrc + row * 1024 + co;
            asm volatile("cp.async.cg.shared.global [%0], [%1], 16;"
                         :: "r"(d), "l"(sp) : "memory");
        }
        asm volatile("cp.async.commit_group;" ::: "memory");
    };
    auto gatherA = [&](int s) {
        const int k = s * 128 + kg * 16 + kl;   // this lane's k-row
#pragma unroll
        for (int i = 0; i < 8; i++) {
            int b = b0 + bh * 8 + i;
            float v = 0.f;
            if (k < KT) {
                if (CELL == 1) {
                    if (k < 3)       v = x[b * (Tc * 3) + t * 3 + k];
                    else if (k < 83) v = __ldcg(&g_w[b * CDc + (k - 3)]);
                    else             v = __ldcg(&h_old[b * Sc + (k - 83)]);
                } else {
                    if (k < 3)        v = x[b * (Tc * 3) + t * 3 + k];
                    else if (k < 515) v = __ldcg(&hin[b * Sc + (k - 3)]);
                    else if (k < 595) v = __ldcg(&g_w[b * CDc + (k - 515)]);
                    else              v = __ldcg(&h_old[b * Sc + (k - 595)]);
                }
            }
            areg[i] = v;
        }
    };
    auto storeA = [&](int buf) {
        float* arow = sm + buf * BUF_F + AS_OFF + kg * (16 * A_PITCH) + kl * A_PITCH
                      + bh * 8;
        *(float4*)(arow)     = make_float4(areg[0], areg[1], areg[2], areg[3]);
        *(float4*)(arow + 4) = make_float4(areg[4], areg[5], areg[6], areg[7]);
    };

    // prologue: first stage (old-state stage for CELL 2/3 — safe at phase entry)
    issueW(ord(0), 0);
    gatherA(ord(0));
    storeA(0);
    asm volatile("cp.async.wait_group 0;" ::: "memory");
    __syncthreads();

    int buf = 0;
    for (int si = 0; si < NS; ++si) {
        // ---- hooks: waits placed stages ahead of the data they protect ----
        if (CELL == 2 && si == 3) {
            g_wait(slot + 0, tgt);       // kgpart(t), h1(t), h3(t-1)... all of step t-1
            attn_inline(sm, c_vec, b_win);   // w(t) for owner batch
            g_arrive(slot + 8);          // c1: w ready
        }
        if (CELL == 2 && si == 7) g_wait(slot + 8, tgt);   // before stage-4 (w) gather
        if (CELL == 3 && si == 3) g_wait(slot + 16, tgt);  // before stage-0 (h2(t)) gather

        if (si + 1 < NS) { issueW(ord(si + 1), buf ^ 1); gatherA(ord(si + 1)); }

        const float* wrow = sm + buf * BUF_F + kg * 1024;
        const float* arow = sm + buf * BUF_F + AS_OFF + kg * (16 * A_PITCH);
#pragma unroll
        for (int k = 0; k < 16; ++k) {
            float4 a  = *(const float4*)(arow + k * A_PITCH + bb * 4);
            float4 w0 = *(const float4*)(wrow + k * 64 + cc * 8);
            float4 w1 = *(const float4*)(wrow + k * 64 + cc * 8 + 4);
            float av[4] = {a.x, a.y, a.z, a.w};
            float wv[8] = {w0.x, w0.y, w0.z, w0.w, w1.x, w1.y, w1.z, w1.w};
#pragma unroll
            for (int ib = 0; ib < 4; ib++)
#pragma unroll
                for (int jc = 0; jc < 8; jc++)
                    acc[ib][jc] += av[ib] * wv[jc];
        }

        if (si + 1 < NS) storeA(buf ^ 1);
        asm volatile("cp.async.wait_group 0;" ::: "memory");
        __syncthreads();
        buf ^= 1;
    }

    // ---- dump k-split partials to red[8][16][64] (reuses buffer 0 area) ----
    float* red = sm;
#pragma unroll
    for (int ib = 0; ib < 4; ib++) {
        int b = bb * 4 + ib;
        float* dst = red + (kg * 16 + b) * 64 + cc * 8;
        *(float4*)(dst)     = make_float4(acc[ib][0], acc[ib][1], acc[ib][2], acc[ib][3]);
        *(float4*)(dst + 4) = make_float4(acc[ib][4], acc[ib][5], acc[ib][6], acc[ib][7]);
    }
    __syncthreads();

    // ---- reduce 8 partials + bias, gate-combine: 2 s-units per thread ----
    {
        const int b_loc = tid >> 4;     // 0..15
        const int sp    = tid & 15;     // 0..15 -> cols sp*4..+3
        float4 e = *(const float4*)&bf[c0 + sp * 4];
#pragma unroll
        for (int g = 0; g < 8; g++) {
            float4 v = *(const float4*)(red + (g * 16 + b_loc) * 64 + sp * 4);
            e.x += v.x; e.y += v.y; e.z += v.z; e.w += v.w;
        }
        const int b  = b0 + b_loc;
        const int s0 = (c0 >> 1) + sp * 2;
        float2 hold = *(const float2*)&h_old[b * Sc + s0];
        float j0 = 1.f / (1.f + __expf(-e.x));
        float k0v = 1.f / (1.f + __expf(-e.y));
        float j1 = 1.f / (1.f + __expf(-e.z));
        float k1v = 1.f / (1.f + __expf(-e.w));
        float2 hn;
        hn.x = j0 * (1.f - hold.x) + (1.f - k0v) * hold.x;
        hn.y = j1 * (1.f - hold.y) + (1.f - k1v) * hold.y;
        *(float2*)&h_new[b * Sc + s0] = hn;
        if (CELL == 3) *(float2*)&g_ys[((size_t)b * Tc + t) * Sc + s0] = hn;
        if (CELL == 1) *(float2*)&sm[AS_OFF + b_loc * 34 + sp * 2] = hn;
    }

    // ---- cell1 only: window-head partials over this block's 32-s slice ----
    if (CELL == 1) {
        __syncthreads();
        const float* ht = sm + AS_OFF;
        if (tid < 240) {
            int bb2 = tid / 15, cp = tid % 15;
            int c  = cp * 2;
            int ct = bid & 15;
            int sbase = ct * 32;
            float a0 = 0.f, a1 = 0.f;
#pragma unroll 4
            for (int s2 = 0; s2 < 32; ++s2) {
                float hv = ht[bb2 * 34 + s2];
                a0 += hv * W_win[(sbase + s2) * 30 + c];
                a1 += hv * W_win[(sbase + s2) * 30 + c + 1];
            }
            g_kgpart[ct][b0 + bb2][c]     = a0;
            g_kgpart[ct][b0 + bb2][c + 1] = a1;
        }
    }
    __syncthreads();
}

// ---------------- persistent RNN kernel (8 independent 16-block groups) ---------
// Split-barrier schedule per step t:
//   phase1: cell2(t): [old stages 5-8] wait_c3 attn arrive_c1 [stages 0-3]
//           wait_c1 [stage 4] epilogue(h2)          -> arrive_c2
//   phase2: cell3(t): [old stages 5-8] wait_c2 [stages 0-4] epilogue(h3,ys);
//           cell1(t+1) (w(t),h1(t) all ready)       -> arrive_c3
__global__ __launch_bounds__(NTHR, 1) void rnn_kernel(
    const float* __restrict__ x, const float* __restrict__ c_vec,
    const float* __restrict__ W_win, const float* __restrict__ b_win)
{
    extern __shared__ float sm[];
    const int group = blockIdx.x >> 4;
    const int slot = group * 32;

    // priming: cell1(0) — reads zeroed state, writes h1(0) + kgpart(0)
    cell_phase<1>(sm, x, W_win, c_vec, b_win, 0, group);
    g_arrive(slot + 0);                     // c3 gen 1

    for (int t = 0; t < Tc; ++t) {
        cell_phase<2>(sm, x, W_win, c_vec, b_win, t, group);
        g_arrive(slot + 16);                // c2: h2(t) ready
        cell_phase<3>(sm, x, W_win, c_vec, b_win, t, group);
        if (t + 1 < Tc)
            cell_phase<1>(sm, x, W_win, c_vec, b_win, t + 1, group);
        g_arrive(slot + 0);                 // c3: step t fully done
    }
}

// ---------------- final projection: out = ys @ W_lin + b_lin --------------------
__global__ __launch_bounds__(256) void final_kernel(
    const float* __restrict__ W_lin, const float* __restrict__ b_lin,
    float* __restrict__ out)
{
    __shared__ __align__(16) float As[16][68];
    __shared__ __align__(16) float Ws[16][128];

    const int tid = threadIdx.x;
    const int tcx = tid & 31;
    const int tr  = tid >> 5;
    const int r0 = blockIdx.x * 64;

    float acc[8][4];
#pragma unroll
    for (int i = 0; i < 8; i++)
#pragma unroll
        for (int j = 0; j < 4; j++) acc[i][j] = 0.f;

    for (int k0 = 0; k0 < Sc; k0 += 16) {
        {
            int r = tid >> 2, q = tid & 3;
            float4 v = *(const float4*)(g_ys + (size_t)(r0 + r) * Sc + k0 + q * 4);
            As[q * 4 + 0][r] = v.x; As[q * 4 + 1][r] = v.y;
            As[q * 4 + 2][r] = v.z; As[q * 4 + 3][r] = v.w;
        }
#pragma unroll
        for (int i = 0; i < 8; i++) {
            int idx = tid + i * 256;
            int r = idx >> 7, c = idx & 127;
            Ws[r][c] = (c < OUTD) ? W_lin[(k0 + r) * OUTD + c] : 0.f;
        }
        __syncthreads();
#pragma unroll
        for (int kk = 0; kk < 16; kk++) {
            float4 a0 = *(const float4*)(&As[kk][tr * 8]);
            float4 a1 = *(const float4*)(&As[kk][tr * 8 + 4]);
            float4 w  = *(const float4*)(&Ws[kk][tcx * 4]);
            float av[8] = {a0.x, a0.y, a0.z, a0.w, a1.x, a1.y, a1.z, a1.w};
#pragma unroll
            for (int i = 0; i < 8; i++) {
                acc[i][0] += av[i] * w.x; acc[i][1] += av[i] * w.y;
                acc[i][2] += av[i] * w.z; acc[i][3] += av[i] * w.w;
            }
        }
        __syncthreads();
    }

#pragma unroll
    for (int i = 0; i < 8; i++) {
        int row = r0 + tr * 8 + i;
#pragma unroll
        for (int j = 0; j < 4; j++) {
            int c = tcx * 4 + j;
            if (c < OUTD) out[(size_t)row * OUTD + c] = acc[i][j] + b_lin[c];
        }
    }
}

// ---------------- launch --------------------------------------------------------
extern "C" void kernel_launch(void* const* d_in, const int* in_sizes, int n_in,
                              void* d_out, int out_size)
{
    const float* x     = (const float*)d_in[0];
    const float* c_vec = (const float*)d_in[1];
    const float* W_win = (const float*)d_in[18];
    const float* b_win = (const float*)d_in[19];
    const float* W_lin = (const float*)d_in[20];
    const float* b_lin = (const float*)d_in[21];

    cudaFuncSetAttribute(rnn_kernel, cudaFuncAttributeMaxDynamicSharedMemorySize,
                         SMEM_BYTES);

    // 3 prep launches — rnn_kernel is launch index 3 (where ncu's capture lands).
    prep_w1<<<512, 256>>>((const float*)d_in[2], (const float*)d_in[6],
                          (const float*)d_in[4], (const float*)d_in[8]);
    prep_w2<<<1024, 256>>>((const float*)d_in[10], (const float*)d_in[14],
                           (const float*)d_in[12], (const float*)d_in[16]);
    prep_misc<<<256, 256>>>((const float*)d_in[3],  (const float*)d_in[5],
                            (const float*)d_in[7],  (const float*)d_in[9],
                            (const float*)d_in[11], (const float*)d_in[13],
                            (const float*)d_in[15], (const float*)d_in[17]);

    rnn_kernel<<<NBLK, NTHR, SMEM_BYTES>>>(x, c_vec, W_win, b_win);

    final_kernel<<<(Bc * Tc) / 64, 256>>>(W_lin, b_lin, (float*)d_out);
}

// round 17
// speedup vs baseline: 1.5310x; 1.4268x over previous
#include <cuda_runtime.h>
#include <math.h>

// Problem constants
#define Bc   128
#define Tc   600
#define Uc   96
#define Kc   10
#define CDc  80
#define Sc   512
#define OUTD 121
#define KT1  595     // cell1 fused K: 3 + 80 + 512
#define KT2  1107    // cell2/3 fused K: 3 + 512 + 80 + 512
#define KP1  640     // 5 stages of 128
#define KP2  1152    // 9 stages of 128
#define NBLK 128
#define NTHR 256

// ---------------- persistent device state (static, no allocations) --------------
__device__ __align__(16) float g_Wf1[KP1 * 1024];  // interleaved j/k cols, zero-padded
__device__ __align__(16) float g_Wf2[KP2 * 1024];
__device__ __align__(16) float g_bf1[1024];
__device__ __align__(16) float g_bf2[1024];
__device__ __align__(16) float g_h1[2][Bc * Sc];
__device__ __align__(16) float g_h2[2][Bc * Sc];
__device__ __align__(16) float g_h3[2][Bc * Sc];
__device__ float g_kappa[Bc * Kc];
__device__ float g_w[Bc * CDc];
__device__ float g_kgpart[16][Bc][30];
__device__ __align__(16) float g_ys[(size_t)Bc * Tc * Sc];
// per-group split-barrier counters: slot base = group*32; +0 = c3 (end of step),
// +8 = c1 (attn/w ready), +16 = c2 (h2 ready). Monotonic, never reset.
__device__ unsigned g_gcnt[8 * 32];

// Dynamic smem layout (floats), stage = 128 k-rows, 8 k-groups x 16 k-rows:
//   two stage buffers, buffer b at b*BUF_F:
//     Ws: 8 groups x 16 k x 64 cols   at +0      (8192 floats)
//     As: 8 groups x 16 k x 20 pitch  at +8192   (2560 floats)
//   post-loop reuse of buffer 0:
//     red:   8 groups x 16 b x 64 cols at +0     (8192 floats)
//     htile: 16 b x 34                 at +8192
//   attn scratch at SC_OFF (128), c_vec slice at CV_OFF (7680),
//   W_win slice at WW_OFF (960) — loaded once, persistent.
#define BUF_F   10752
#define AS_OFF  8192
#define A_PITCH 20
#define SC_OFF  (2 * BUF_F)
#define CV_OFF  (SC_OFF + 128)
#define WW_OFF  (CV_OFF + Uc * CDc)
#define SMEM_F  (WW_OFF + 32 * 30)
#define SMEM_BYTES (SMEM_F * 4)

// ---------------- split group barrier: arrive / wait ----------------------------
__device__ __forceinline__ void g_arrive(int slot)
{
    __threadfence();
    __syncthreads();
    if (threadIdx.x == 0) atomicAdd(&g_gcnt[slot], 1);
}
__device__ __forceinline__ void g_wait(int slot, unsigned target)
{
    if (threadIdx.x == 0) {
        while (*(volatile unsigned*)&g_gcnt[slot] < target) { }
    }
    __syncthreads();
}

// ---------------- prep kernels (3 launches; ncu capture lands on rnn) -----------
__global__ void prep_w1(const float* __restrict__ Wjx1, const float* __restrict__ Wkx1,
                        const float* __restrict__ Wjh1, const float* __restrict__ Wkh1)
{
    const int stride = gridDim.x * blockDim.x;
    for (int idx = blockIdx.x * blockDim.x + threadIdx.x; idx < KP1 * 1024; idx += stride) {
        int d = idx >> 10, c = idx & 1023;
        int s = c >> 1, isk = c & 1;
        float v = 0.f;
        if (d < 83)        v = isk ? Wkx1[d * Sc + s] : Wjx1[d * Sc + s];
        else if (d < KT1)  v = isk ? Wkh1[(d - 83) * Sc + s] : Wjh1[(d - 83) * Sc + s];
        g_Wf1[idx] = v;
    }
}

__global__ void prep_w2(const float* __restrict__ Wjx2, const float* __restrict__ Wkx2,
                        const float* __restrict__ Wjh2, const float* __restrict__ Wkh2)
{
    const int stride = gridDim.x * blockDim.x;
    for (int idx = blockIdx.x * blockDim.x + threadIdx.x; idx < KP2 * 1024; idx += stride) {
        int d = idx >> 10, c = idx & 1023;
        int s = c >> 1, isk = c & 1;
        float v = 0.f;
        if (d < 595)       v = isk ? Wkx2[d * Sc + s] : Wjx2[d * Sc + s];
        else if (d < KT2)  v = isk ? Wkh2[(d - 595) * Sc + s] : Wjh2[(d - 595) * Sc + s];
        g_Wf2[idx] = v;
    }
}

__global__ void prep_misc(const float* __restrict__ bjx1, const float* __restrict__ bjh1,
                          const float* __restrict__ bkx1, const float* __restrict__ bkh1,
                          const float* __restrict__ bjx2, const float* __restrict__ bjh2,
                          const float* __restrict__ bkx2, const float* __restrict__ bkh2)
{
    const int stride = gridDim.x * blockDim.x;
    const int t0 = blockIdx.x * blockDim.x + threadIdx.x;
    for (int i = t0; i < 8 * 32; i += stride) g_gcnt[i] = 0;
    for (int idx = t0; idx < 1024; idx += stride) {
        int s = idx >> 1, isk = idx & 1;
        g_bf1[idx] = isk ? (bkx1[s] + bkh1[s]) : (bjx1[s] + bjh1[s]);
        g_bf2[idx] = isk ? (bkx2[s] + bkh2[s]) : (bjx2[s] + bjh2[s]);
    }
    for (int idx = t0; idx < Bc * Sc; idx += stride) {
        g_h1[0][idx] = 0.f; g_h1[1][idx] = 0.f;
        g_h2[0][idx] = 0.f; g_h2[1][idx] = 0.f;
        g_h3[0][idx] = 0.f; g_h3[1][idx] = 0.f;
    }
    for (int idx = t0; idx < Bc * CDc; idx += stride) g_w[idx] = 0.f;
    for (int idx = t0; idx < Bc * Kc; idx += stride) g_kappa[idx] = 0.f;
}

// ---------------- attention (owner batch) — inlined into cell2 phase ------------
// c_vec slice for the owner batch lives in smem (loaded once at kernel start).
__device__ void attn_inline(float* sm, const float* __restrict__ b_win)
{
    const int b = blockIdx.x;     // block (g,ct) owns batch g*16+ct == blockIdx.x
    const int tid = threadIdx.x;
    float* abk = sm + SC_OFF;      // [32]
    float* phi = sm + SC_OFF + 32; // [96]

    if (tid < 30) {
        float v = b_win[tid];
#pragma unroll
        for (int ct = 0; ct < 16; ++ct) v += __ldcg(&g_kgpart[ct][b][tid]);
        float e = __expf(v);
        if (tid >= 20) {
            int i = b * Kc + (tid - 20);
            float kn = g_kappa[i] + e;     // owner-only access
            g_kappa[i] = kn;
            abk[tid] = kn;
        } else {
            abk[tid] = e;
        }
    }
    __syncthreads();

    if (tid < Uc) {
        float u = (float)tid;
        float p = 0.f;
#pragma unroll
        for (int k = 0; k < Kc; ++k) {
            float d = abk[20 + k] - u;
            p += abk[k] * __expf(-abk[10 + k] * d * d);
        }
        phi[tid] = p;
    }
    __syncthreads();

    if (tid < CDc) {
        float acc = 0.f;
        const float* cv = sm + CV_OFF + tid;
#pragma unroll 4
        for (int u = 0; u < Uc; ++u) acc += phi[u] * cv[u * CDc];
        g_w[b * CDc + tid] = acc;
    }
    // visibility handled by g_arrive (fence + sync) right after
}

// ---------------- gated-cell GEMM phase -----------------------------------------
// Tile 16b x 64c; 8 warps = 8 k-groups of 16 k-rows per 128-k stage; thread tile
// 4b x 8c (cols cc*4..+3 and 32+cc*4..+3 — conflict-free 128B w-reads);
// scalar FFMA; cp.async double-buffered W tiles.
// CELL 2/3 stage order: [5,6,7,8, 0,1,2,3,4] — old-state stages first, so the
// cross-block waits (and attn for CELL 2) hide behind dependency-free compute.
template <int CELL>
__device__ void cell_phase(float* sm, const float* __restrict__ x,
                           const float* __restrict__ b_win,
                           int t, int group)
{
    constexpr int KT = (CELL == 1) ? KT1 : KT2;
    constexpr int NS = (CELL == 1) ? 5 : 9;

    const int pi = t & 1;
    const float* __restrict__ Wf    = (CELL == 1) ? g_Wf1 : g_Wf2;
    const float* __restrict__ bf    = (CELL == 1) ? g_bf1 : g_bf2;
    const float* __restrict__ h_old = (CELL == 1) ? g_h1[pi ^ 1]
                                   : (CELL == 2) ? g_h2[pi ^ 1] : g_h3[pi ^ 1];
    float* __restrict__       h_new = (CELL == 1) ? g_h1[pi]
                                   : (CELL == 2) ? g_h2[pi] : g_h3[pi];
    const float* __restrict__ hin   = (CELL == 2) ? g_h1[pi] : g_h2[pi];

    const int tid  = threadIdx.x;
    const int kg   = tid >> 5;      // warp = k-group 0..7
    const int lane = tid & 31;
    const int bb   = lane >> 3;     // 0..3 -> 4 b's each (FMA loop)
    const int cc   = lane & 7;      // 0..7 -> cols cc*4..+3 and 32+cc*4..+3
    const int kl   = lane & 15;     // k-row within group (gather/store)
    const int bh   = lane >> 4;     // batch half (gather/store)
    const int bid  = blockIdx.x;
    const int c0 = (bid & 15) * 64;
    const int b0 = (bid >> 4) * 16;
    const int slot = group * 32;
    const unsigned tgt = (unsigned)(t + 1) * 16u;

    const unsigned smbase = (unsigned)__cvta_generic_to_shared(sm);

    float acc[4][8];
#pragma unroll
    for (int i = 0; i < 4; i++)
#pragma unroll
        for (int j = 0; j < 8; j++) acc[i][j] = 0.f;

    float areg[8];

    auto ord = [&](int si) -> int {
        return (CELL == 1) ? si : (si < 4 ? si + 5 : si - 4);
    };
    auto issueW = [&](int s, int buf) {
        const int k0 = s * 128 + kg * 16;
        const float* wsrc = Wf + (size_t)k0 * 1024 + c0;
        unsigned dst = smbase + (unsigned)((buf * BUF_F + kg * 1024) * 4);
#pragma unroll
        for (int i = 0; i < 8; i++) {
            int idx = lane + i * 32;          // 0..255 float4 slots (16 rows x 16)
            int row = idx >> 4, co = (idx & 15) * 4;
            unsigned d = dst + (unsigned)((row * 64 + co) * 4);
            const float* sp = wsrc + row * 1024 + co;
            asm volatile("cp.async.cg.shared.global [%0], [%1], 16;"
                         :: "r"(d), "l"(sp) : "memory");
        }
        asm volatile("cp.async.commit_group;" ::: "memory");
    };
    auto gatherA = [&](int s) {
        const int k = s * 128 + kg * 16 + kl;   // this lane's k-row
#pragma unroll
        for (int i = 0; i < 8; i++) {
            int b = b0 + bh * 8 + i;
            float v = 0.f;
            if (k < KT) {
                if (CELL == 1) {
                    if (k < 3)       v = x[b * (Tc * 3) + t * 3 + k];
                    else if (k < 83) v = __ldcg(&g_w[b * CDc + (k - 3)]);
                    else             v = __ldcg(&h_old[b * Sc + (k - 83)]);
                } else {
                    if (k < 3)        v = x[b * (Tc * 3) + t * 3 + k];
                    else if (k < 515) v = __ldcg(&hin[b * Sc + (k - 3)]);
                    else if (k < 595) v = __ldcg(&g_w[b * CDc + (k - 515)]);
                    else              v = __ldcg(&h_old[b * Sc + (k - 595)]);
                }
            }
            areg[i] = v;
        }
    };
    auto storeA = [&](int buf) {
        float* arow = sm + buf * BUF_F + AS_OFF + kg * (16 * A_PITCH) + kl * A_PITCH
                      + bh * 8;
        *(float4*)(arow)     = make_float4(areg[0], areg[1], areg[2], areg[3]);
        *(float4*)(arow + 4) = make_float4(areg[4], areg[5], areg[6], areg[7]);
    };

    // prologue: first stage (old-state stage for CELL 2/3 — safe at phase entry)
    issueW(ord(0), 0);
    gatherA(ord(0));
    storeA(0);
    asm volatile("cp.async.wait_group 0;" ::: "memory");
    __syncthreads();

    int buf = 0;
    for (int si = 0; si < NS; ++si) {
        // ---- hooks: waits placed stages ahead of the data they protect ----
        if (CELL == 2 && si == 3) {
            g_wait(slot + 0, tgt);       // all of step t-1 done
            attn_inline(sm, b_win);      // w(t) for owner batch
            g_arrive(slot + 8);          // c1: w ready
        }
        if (CELL == 2 && si == 7) g_wait(slot + 8, tgt);   // before stage-4 (w) gather
        if (CELL == 3 && si == 3) g_wait(slot + 16, tgt);  // before stage-0 (h2(t)) gather

        if (si + 1 < NS) { issueW(ord(si + 1), buf ^ 1); gatherA(ord(si + 1)); }

        const float* wrow = sm + buf * BUF_F + kg * 1024;
        const float* arow = sm + buf * BUF_F + AS_OFF + kg * (16 * A_PITCH);
#pragma unroll
        for (int k = 0; k < 16; ++k) {
            float4 a  = *(const float4*)(arow + k * A_PITCH + bb * 4);
            float4 w0 = *(const float4*)(wrow + k * 64 + cc * 4);       // 128B span
            float4 w1 = *(const float4*)(wrow + k * 64 + 32 + cc * 4);  // 128B span
            float av[4] = {a.x, a.y, a.z, a.w};
            float wv[8] = {w0.x, w0.y, w0.z, w0.w, w1.x, w1.y, w1.z, w1.w};
#pragma unroll
            for (int ib = 0; ib < 4; ib++)
#pragma unroll
                for (int jc = 0; jc < 8; jc++)
                    acc[ib][jc] += av[ib] * wv[jc];
        }

        if (si + 1 < NS) storeA(buf ^ 1);
        asm volatile("cp.async.wait_group 0;" ::: "memory");
        __syncthreads();
        buf ^= 1;
    }

    // ---- dump k-split partials to red[8][16][64] (reuses buffer 0 area) ----
    // acc[ib][0..3] -> cols cc*4..+3 ; acc[ib][4..7] -> cols 32+cc*4..+3
    float* red = sm;
#pragma unroll
    for (int ib = 0; ib < 4; ib++) {
        int b = bb * 4 + ib;
        float* dst = red + (kg * 16 + b) * 64;
        *(float4*)(dst + cc * 4)      = make_float4(acc[ib][0], acc[ib][1], acc[ib][2], acc[ib][3]);
        *(float4*)(dst + 32 + cc * 4) = make_float4(acc[ib][4], acc[ib][5], acc[ib][6], acc[ib][7]);
    }
    __syncthreads();

    // ---- reduce 8 partials + bias, gate-combine: 2 s-units per thread ----
    {
        const int b_loc = tid >> 4;     // 0..15
        const int sp    = tid & 15;     // 0..15 -> cols sp*4..+3
        float4 e = *(const float4*)&bf[c0 + sp * 4];
#pragma unroll
        for (int g = 0; g < 8; g++) {
            float4 v = *(const float4*)(red + (g * 16 + b_loc) * 64 + sp * 4);
            e.x += v.x; e.y += v.y; e.z += v.z; e.w += v.w;
        }
        const int b  = b0 + b_loc;
        const int s0 = (c0 >> 1) + sp * 2;
        float2 hold = *(const float2*)&h_old[b * Sc + s0];
        float j0 = 1.f / (1.f + __expf(-e.x));
        float k0v = 1.f / (1.f + __expf(-e.y));
        float j1 = 1.f / (1.f + __expf(-e.z));
        float k1v = 1.f / (1.f + __expf(-e.w));
        float2 hn;
        hn.x = j0 * (1.f - hold.x) + (1.f - k0v) * hold.x;
        hn.y = j1 * (1.f - hold.y) + (1.f - k1v) * hold.y;
        *(float2*)&h_new[b * Sc + s0] = hn;
        if (CELL == 3) *(float2*)&g_ys[((size_t)b * Tc + t) * Sc + s0] = hn;
        if (CELL == 1) *(float2*)&sm[AS_OFF + b_loc * 34 + sp * 2] = hn;
    }

    // ---- cell1 only: window-head partials over this block's 32-s slice ----
    if (CELL == 1) {
        __syncthreads();
        const float* ht = sm + AS_OFF;
        const float* ww = sm + WW_OFF;   // W_win rows (ct*32..+32), cached in smem
        if (tid < 240) {
            int bb2 = tid / 15, cp = tid % 15;
            int c  = cp * 2;
            int ct = bid & 15;
            float a0 = 0.f, a1 = 0.f;
#pragma unroll 4
            for (int s2 = 0; s2 < 32; ++s2) {
                float hv = ht[bb2 * 34 + s2];
                a0 += hv * ww[s2 * 30 + c];
                a1 += hv * ww[s2 * 30 + c + 1];
            }
            g_kgpart[ct][b0 + bb2][c]     = a0;
            g_kgpart[ct][b0 + bb2][c + 1] = a1;
        }
    }
    __syncthreads();
}

// ---------------- persistent RNN kernel (8 independent 16-block groups) ---------
__global__ __launch_bounds__(NTHR, 1) void rnn_kernel(
    const float* __restrict__ x, const float* __restrict__ c_vec,
    const float* __restrict__ W_win, const float* __restrict__ b_win)
{
    extern __shared__ float sm[];
    const int group = blockIdx.x >> 4;
    const int slot = group * 32;
    const int tid = threadIdx.x;

    // one-time smem caches (inputs are constant across the whole sequence)
    {
        const float* cv = c_vec + (size_t)blockIdx.x * (Uc * CDc);
        for (int i = tid; i < Uc * CDc; i += NTHR) sm[CV_OFF + i] = cv[i];
        const int sbase = (blockIdx.x & 15) * 32;
        for (int i = tid; i < 32 * 30; i += NTHR) sm[WW_OFF + i] = W_win[sbase * 30 + i];
    }
    __syncthreads();

    // priming: cell1(0) — reads zeroed state, writes h1(0) + kgpart(0)
    cell_phase<1>(sm, x, b_win, 0, group);
    g_arrive(slot + 0);                     // c3 gen 1

    for (int t = 0; t < Tc; ++t) {
        cell_phase<2>(sm, x, b_win, t, group);
        g_arrive(slot + 16);                // c2: h2(t) ready
        cell_phase<3>(sm, x, b_win, t, group);
        if (t + 1 < Tc)
            cell_phase<1>(sm, x, b_win, t + 1, group);
        g_arrive(slot + 0);                 // c3: step t fully done
    }
}

// ---------------- final projection: out = ys @ W_lin + b_lin --------------------
__global__ __launch_bounds__(256) void final_kernel(
    const float* __restrict__ W_lin, const float* __restrict__ b_lin,
    float* __restrict__ out)
{
    __shared__ __align__(16) float As[16][68];
    __shared__ __align__(16) float Ws[16][128];

    const int tid = threadIdx.x;
    const int tcx = tid & 31;
    const int tr  = tid >> 5;
    const int r0 = blockIdx.x * 64;

    float acc[8][4];
#pragma unroll
    for (int i = 0; i < 8; i++)
#pragma unroll
        for (int j = 0; j < 4; j++) acc[i][j] = 0.f;

    for (int k0 = 0; k0 < Sc; k0 += 16) {
        {
            int r = tid >> 2, q = tid & 3;
            float4 v = *(const float4*)(g_ys + (size_t)(r0 + r) * Sc + k0 + q * 4);
            As[q * 4 + 0][r] = v.x; As[q * 4 + 1][r] = v.y;
            As[q * 4 + 2][r] = v.z; As[q * 4 + 3][r] = v.w;
        }
#pragma unroll
        for (int i = 0; i < 8; i++) {
            int idx = tid + i * 256;
            int r = idx >> 7, c = idx & 127;
            Ws[r][c] = (c < OUTD) ? W_lin[(k0 + r) * OUTD + c] : 0.f;
        }
        __syncthreads();
#pragma unroll
        for (int kk = 0; kk < 16; kk++) {
            float4 a0 = *(const float4*)(&As[kk][tr * 8]);
            float4 a1 = *(const float4*)(&As[kk][tr * 8 + 4]);
            float4 w  = *(const float4*)(&Ws[kk][tcx * 4]);
            float av[8] = {a0.x, a0.y, a0.z, a0.w, a1.x, a1.y, a1.z, a1.w};
#pragma unroll
            for (int i = 0; i < 8; i++) {
                acc[i][0] += av[i] * w.x; acc[i][1] += av[i] * w.y;
                acc[i][2] += av[i] * w.z; acc[i][3] += av[i] * w.w;
            }
        }
        __syncthreads();
    }

#pragma unroll
    for (int i = 0; i < 8; i++) {
        int row = r0 + tr * 8 + i;
#pragma unroll
        for (int j = 0; j < 4; j++) {
            int c = tcx * 4 + j;
            if (c < OUTD) out[(size_t)row * OUTD + c] = acc[i][j] + b_lin[c];
        }
    }
}

// ---------------- launch --------------------------------------------------------
extern "C" void kernel_launch(void* const* d_in, const int* in_sizes, int n_in,
                              void* d_out, int out_size)
{
    const float* x     = (const float*)d_in[0];
    const float* c_vec = (const float*)d_in[1];
    const float* W_win = (const float*)d_in[18];
    const float* b_win = (const float*)d_in[19];
    const float* W_lin = (const float*)d_in[20];
    const float* b_lin = (const float*)d_in[21];

    cudaFuncSetAttribute(rnn_kernel, cudaFuncAttributeMaxDynamicSharedMemorySize,
                         SMEM_BYTES);

    // 3 prep launches — rnn_kernel is launch index 3 (ncu capture lands on it).
    prep_w1<<<512, 256>>>((const float*)d_in[2], (const float*)d_in[6],
                          (const float*)d_in[4], (const float*)d_in[8]);
    prep_w2<<<1024, 256>>>((const float*)d_in[10], (const float*)d_in[14],
                           (const float*)d_in[12], (const float*)d_in[16]);
    prep_misc<<<256, 256>>>((const float*)d_in[3],  (const float*)d_in[5],
                            (const float*)d_in[7],  (const float*)d_in[9],
                            (const float*)d_in[11], (const float*)d_in[13],
                            (const float*)d_in[15], (const float*)d_in[17]);

    rnn_kernel<<<NBLK, NTHR, SMEM_BYTES>>>(x, c_vec, W_win, b_win);

    final_kernel<<<(Bc * Tc) / 64, 256>>>(W_lin, b_lin, (float*)d_out);
}